// round 3
// baseline (speedup 1.0000x reference)
#include <cuda_runtime.h>
#include <math.h>

// Problem constants
#define B    64
#define SEQ  512
#define H    1024
#define V    128
#define OUTD 128

// Recurrence kernel config
#define G    128           // persistent CTAs (<= 148 SMs => co-resident, spin barrier safe)
#define CPC  8             // columns of W_hh per CTA (H / G)
#define NT   256           // threads per CTA
#define NW   8             // warps per CTA
#define KC   (H / NW)      // 128 k-values per warp

static_assert(G * CPC == H, "partition");
static_assert(NW * KC == H, "k split");

// Scratch (device globals: allocation-free rule). Zero-initialized at module load.
__device__ float g_hs[(size_t)SEQ * H * B];  // hidden states, layout [t][h][b]  (128 MB)
__device__ float g_h0[H * B];                // initial h = 0 (never written)
__device__ unsigned g_arrive = 0;
__device__ volatile unsigned g_release = 0;

// ---------------------------------------------------------------------------
// Grid-wide barrier (two-variable, generation counter). Only valid because all
// G CTAs are co-resident (G <= SM count, 1 CTA/SM). State is self-restoring
// across graph replays (g_arrive returns to 0; g_release monotonic).
// ---------------------------------------------------------------------------
__device__ __forceinline__ void grid_sync() {
    __syncthreads();
    if (threadIdx.x == 0) {
        __threadfence();                       // publish this CTA's g_hs writes
        unsigned gen = g_release;
        if (atomicAdd(&g_arrive, 1u) == G - 1u) {
            g_arrive = 0;
            __threadfence();
            g_release = gen + 1u;              // sole writer for this generation
        } else {
            while (g_release == gen) { }
        }
        __threadfence();                       // acquire other CTAs' writes
    }
    __syncthreads();
}

__device__ __forceinline__ float tanh_safe(float x) {
    // tanh(x) = sign(x) * (1 - 2/(exp(2|x|)+1)); overflow-safe (exp->inf => 1).
    float ax = fabsf(x);
    float e  = __expf(2.0f * ax);
    float r  = 1.0f - 2.0f / (e + 1.0f);
    return copysignf(r, x);
}

// ---------------------------------------------------------------------------
// Persistent recurrence kernel.
//   h_t = tanh(h_{t-1} @ W_hh + W_xh[X[:,t]] + b_h)
// CTA c owns output columns [c*8, c*8+8). W slice lives in smem all 512 steps.
// Warps split the k (=H) reduction dim; partials combined through smem.
// h stored transposed [h][b] so the broadcast reads are coalesced LDG.128.
// ---------------------------------------------------------------------------
__global__ void __launch_bounds__(NT, 1)
rnn_recurrence_kernel(const int* __restrict__ X,
                      const float* __restrict__ W_hh,
                      const float* __restrict__ W_xh,
                      const float* __restrict__ b_h) {
    extern __shared__ float sm[];
    float* ws  = sm;                        // [H][CPC]            32 KB
    float* red = sm + H * CPC;              // [NW][B][9] padded   18 KB
    int*   tok = (int*)(red + NW * B * 9);  // [B]

    const int tid = threadIdx.x;
    const int c0  = blockIdx.x * CPC;

    // One-time load of this CTA's W_hh column slice into smem (k-major rows of 8).
    for (int i = tid; i < H * CPC; i += NT) {
        int k = i >> 3, jj = i & 7;
        ws[i] = W_hh[(size_t)k * H + c0 + jj];
    }

    const int w    = tid >> 5;
    const int lane = tid & 31;
    const int j2   = lane & 1;        // which 4-column half
    const int b4   = lane >> 1;       // which 4-batch group (0..15)
    const int bb0  = b4 * 4;
    const int jb0  = j2 * 4;

    // Precompute reduction-phase mapping (2 outputs per thread).
    const int o0 = tid,        j0 = o0 >> 6, bo0 = o0 & 63;
    const int o1 = tid + NT,   j1 = o1 >> 6, bo1 = o1 & 63;
    const float bh0 = b_h[c0 + j0];
    const float bh1 = b_h[c0 + j1];

    __syncthreads();

    for (int t = 0; t < SEQ; t++) {
        const float* hp = (t == 0) ? g_h0 : (g_hs + (size_t)(t - 1) * H * B);

        if (tid < B) tok[tid] = X[tid * SEQ + t];

        // Per-warp partial: 4x4 outer-product tile over this warp's k-chunk.
        float a[4][4] = {};
        const float* hbase  = hp + bb0;
        const float* wsbase = ws + jb0;
        const int kbeg = w * KC;
        #pragma unroll 8
        for (int kk = 0; kk < KC; kk++) {
            const int k = kbeg + kk;
            float4 hv = *(const float4*)(hbase  + (size_t)k * B);
            float4 wv = *(const float4*)(wsbase + k * CPC);
            float hvv[4] = {hv.x, hv.y, hv.z, hv.w};
            float wvv[4] = {wv.x, wv.y, wv.z, wv.w};
            #pragma unroll
            for (int bi = 0; bi < 4; bi++)
                #pragma unroll
                for (int ji = 0; ji < 4; ji++)
                    a[bi][ji] = fmaf(hvv[bi], wvv[ji], a[bi][ji]);
        }

        // Stash partials: red[w][b][j], j-stride padded to 9 (conflict-free reads).
        float* rbase = red + w * (B * 9) + bb0 * 9 + jb0;
        #pragma unroll
        for (int bi = 0; bi < 4; bi++)
            #pragma unroll
            for (int ji = 0; ji < 4; ji++)
                rbase[bi * 9 + ji] = a[bi][ji];

        __syncthreads();

        // Reduce 8 warps + input proj + bias + tanh; write h_t transposed.
        {
            float s0 = 0.f, s1 = 0.f;
            #pragma unroll
            for (int ww = 0; ww < NW; ww++) {
                s0 += red[ww * (B * 9) + bo0 * 9 + j0];
                s1 += red[ww * (B * 9) + bo1 * 9 + j1];
            }
            int tk0 = tok[bo0], tk1 = tok[bo1];
            float x0 = s0 + W_xh[(size_t)tk0 * H + c0 + j0] + bh0;
            float x1 = s1 + W_xh[(size_t)tk1 * H + c0 + j1] + bh1;
            float* hout = g_hs + (size_t)t * H * B;
            hout[(size_t)(c0 + j0) * B + bo0] = tanh_safe(x0);
            hout[(size_t)(c0 + j1) * B + bo1] = tanh_safe(x1);
        }

        grid_sync();
    }
}

// ---------------------------------------------------------------------------
// Output projection: out[b][t][o] = sum_h hs[t][h][b] * W_hy[h][o] + b_y[o]
// One CTA per timestep; k-chunked smem-staged GEMM, 4x8 register tile/thread.
// ---------------------------------------------------------------------------
__global__ void __launch_bounds__(256)
rnn_output_kernel(const float* __restrict__ W_hy,
                  const float* __restrict__ b_y,
                  float* __restrict__ out) {
    __shared__ float hc[64 * 64];    // [k][b] chunk   16 KB
    __shared__ float Wc[64 * OUTD];  // [k][o] chunk   32 KB

    const int t   = blockIdx.x;
    const int tid = threadIdx.x;
    const int b4  = tid & 15;
    const int o8  = tid >> 4;
    const int b0  = b4 * 4;
    const int o0  = o8 * 8;

    float acc[4][8] = {};
    const float* hsrc = g_hs + (size_t)t * H * B;

    for (int k0 = 0; k0 < H; k0 += 64) {
        // Stage h chunk [64 k][64 b] and W chunk [64 k][128 o]
        const float4* hsv = (const float4*)(hsrc + (size_t)k0 * B);
        float4* hcv = (float4*)hc;
        #pragma unroll
        for (int i = 0; i < 4; i++) hcv[tid + i * 256] = hsv[tid + i * 256];

        const float4* wsv = (const float4*)(W_hy + (size_t)k0 * OUTD);
        float4* wcv = (float4*)Wc;
        #pragma unroll
        for (int i = 0; i < 8; i++) wcv[tid + i * 256] = wsv[tid + i * 256];

        __syncthreads();

        #pragma unroll 4
        for (int k = 0; k < 64; k++) {
            float4 hv = *(const float4*)(hc + k * 64 + b0);
            float4 w0 = *(const float4*)(Wc + k * OUTD + o0);
            float4 w1 = *(const float4*)(Wc + k * OUTD + o0 + 4);
            float hvv[4] = {hv.x, hv.y, hv.z, hv.w};
            float wvv[8] = {w0.x, w0.y, w0.z, w0.w, w1.x, w1.y, w1.z, w1.w};
            #pragma unroll
            for (int bi = 0; bi < 4; bi++)
                #pragma unroll
                for (int oi = 0; oi < 8; oi++)
                    acc[bi][oi] = fmaf(hvv[bi], wvv[oi], acc[bi][oi]);
        }
        __syncthreads();
    }

    float4 by0 = *(const float4*)(b_y + o0);
    float4 by1 = *(const float4*)(b_y + o0 + 4);
    float byv[8] = {by0.x, by0.y, by0.z, by0.w, by1.x, by1.y, by1.z, by1.w};

    #pragma unroll
    for (int bi = 0; bi < 4; bi++) {
        float* dst = out + ((size_t)(b0 + bi) * SEQ + t) * OUTD + o0;
        float4 v0, v1;
        v0.x = acc[bi][0] + byv[0]; v0.y = acc[bi][1] + byv[1];
        v0.z = acc[bi][2] + byv[2]; v0.w = acc[bi][3] + byv[3];
        v1.x = acc[bi][4] + byv[4]; v1.y = acc[bi][5] + byv[5];
        v1.z = acc[bi][6] + byv[6]; v1.w = acc[bi][7] + byv[7];
        *(float4*)(dst)     = v0;
        *(float4*)(dst + 4) = v1;
    }
}

// ---------------------------------------------------------------------------
// Launch. Inputs (metadata order): X[i32 64x512], W_hh[f32 1024x1024],
// W_xh[f32 128x1024], W_hy[f32 1024x128], b_h[1024], b_y[128].
// Output: f32 [64][512][128].
// ---------------------------------------------------------------------------
extern "C" void kernel_launch(void* const* d_in, const int* in_sizes, int n_in,
                              void* d_out, int out_size) {
    const int*   X    = (const int*)  d_in[0];
    const float* W_hh = (const float*)d_in[1];
    const float* W_xh = (const float*)d_in[2];
    const float* W_hy = (const float*)d_in[3];
    const float* b_h  = (const float*)d_in[4];
    const float* b_y  = (const float*)d_in[5];
    float* out = (float*)d_out;

    const int smem_rnn = (H * CPC + NW * B * 9) * (int)sizeof(float) + B * (int)sizeof(int);
    cudaFuncSetAttribute(rnn_recurrence_kernel,
                         cudaFuncAttributeMaxDynamicSharedMemorySize, smem_rnn);

    rnn_recurrence_kernel<<<G, NT, smem_rnn>>>(X, W_hh, W_xh, b_h);
    rnn_output_kernel<<<SEQ, 256>>>(W_hy, b_y, out);
}

// round 4
// speedup vs baseline: 1.2771x; 1.2771x over previous
#include <cuda_runtime.h>
#include <math.h>

// Problem constants
#define B    64
#define SEQ  512
#define H    1024
#define OUTD 128

// Recurrence config
#define G    128           // persistent CTAs (<= 148 SMs => co-resident, spin barrier safe)
#define CPC  8             // columns of W_hh per CTA (H / G)
#define NT   256
#define NW   8             // warps per CTA
#define KC   (H / NW)      // 128 k per warp; processed as 64 k-pairs (lane k-parity split)
#define NSLOT (2 * NW)     // 16 partial slots (warp x k-parity)
#define SLOTSTRIDE 577     // 64*9 + 1 pad: breaks bank aliasing between slots

static_assert(G * CPC == H, "partition");

typedef unsigned long long u64;

// Scratch (device globals: allocation-free rule). Zero-initialized at module load.
__device__ float g_hs[(size_t)SEQ * H * B];  // hidden states [t][h][b]
__device__ float g_h0[H * B];                // initial h = 0 (never written)
__device__ unsigned g_arrive = 0;
__device__ volatile unsigned g_release = 0;

// ---------------------------------------------------------------------------
// Packed f32x2 helpers (Blackwell FFMA2: 2 fp32 FMAs per instruction)
// ---------------------------------------------------------------------------
__device__ __forceinline__ u64 dup2(float x) {
    u64 r; unsigned u = __float_as_uint(x);
    asm("mov.b64 %0, {%1, %2};" : "=l"(r) : "r"(u), "r"(u));
    return r;
}
__device__ __forceinline__ void ffma2(u64& d, u64 a, u64 b) {
    asm("fma.rn.f32x2 %0, %1, %2, %3;" : "=l"(d) : "l"(a), "l"(b), "l"(d));
}
__device__ __forceinline__ void unpack2(u64 v, float& x, float& y) {
    unsigned lo, hi;
    asm("mov.b64 {%0, %1}, %2;" : "=r"(lo), "=r"(hi) : "l"(v));
    x = __uint_as_float(lo); y = __uint_as_float(hi);
}

// ---------------------------------------------------------------------------
// Grid-wide barrier (unchanged from passing R2 kernel).
// ---------------------------------------------------------------------------
__device__ __forceinline__ void grid_sync() {
    __syncthreads();
    if (threadIdx.x == 0) {
        __threadfence();
        unsigned gen = g_release;
        if (atomicAdd(&g_arrive, 1u) == G - 1u) {
            g_arrive = 0;
            __threadfence();
            g_release = gen + 1u;
        } else {
            while (g_release == gen) { }
        }
        __threadfence();
    }
    __syncthreads();
}

__device__ __forceinline__ float tanh_safe(float x) {
    float ax = fabsf(x);
    float e  = __expf(2.0f * ax);
    float r  = 1.0f - 2.0f / (e + 1.0f);
    return copysignf(r, x);
}

// ---------------------------------------------------------------------------
// Persistent recurrence: h_t = tanh(h_{t-1} @ W_hh + W_xh[X[:,t]] + b_h)
// CTA c owns columns [c*8, c*8+8). W slice resident in smem all 512 steps.
// Lane tile: 4 batches x 8 columns, k split across warps (8x) and lane
// k-parity (2x). Each 16B of h read exactly once per CTA.
// ---------------------------------------------------------------------------
__global__ void __launch_bounds__(NT, 1)
rnn_recurrence_kernel(const int* __restrict__ X,
                      const float* __restrict__ W_hh,
                      const float* __restrict__ W_xh,
                      const float* __restrict__ b_h) {
    extern __shared__ float sm[];
    float* ws  = sm;                              // [H][CPC]   32 KB
    float* red = sm + H * CPC;                    // [16][577]  ~36 KB
    int*   tok = (int*)(red + NSLOT * SLOTSTRIDE);

    const int tid = threadIdx.x;
    const int c0  = blockIdx.x * CPC;

    // One-time W_hh slice load (k-major rows of 8 columns)
    for (int i = tid; i < H * CPC; i += NT) {
        int k = i >> 3, j = i & 7;
        ws[i] = W_hh[(size_t)k * H + c0 + j];
    }

    const int w    = tid >> 5;
    const int lane = tid & 31;
    const int b4   = lane & 15;     // batch group (4 batches)
    const int kpar = lane >> 4;     // k parity within warp
    const int bb0  = b4 * 4;
    const int slot = w * 2 + kpar;
    float* rstore  = red + slot * SLOTSTRIDE + bb0 * 9;

    // Reduction mapping: 2 outputs per thread: (jr0, br) and (jr0+4, br)
    const int jr0 = tid >> 6;       // 0..3
    const int br  = tid & 63;
    const float bh0 = b_h[c0 + jr0];
    const float bh1 = b_h[c0 + jr0 + 4];

    __syncthreads();

    for (int t = 0; t < SEQ; t++) {
        const float* hp = t ? (g_hs + (size_t)(t - 1) * H * B) : g_h0;
        if (tid < B) tok[tid] = X[tid * SEQ + t];

        u64 acc[4][4];
        #pragma unroll
        for (int bi = 0; bi < 4; bi++)
            #pragma unroll
            for (int jp = 0; jp < 4; jp++) acc[bi][jp] = 0ull;

        const float* hb = hp + (size_t)(w * KC + kpar) * B + bb0;
        const float* wb = ws + (w * KC + kpar) * CPC;

        #pragma unroll 8
        for (int it = 0; it < KC / 2; it++) {
            float4 hv = *(const float4*)(hb + (size_t)it * 2 * B);
            ulonglong2 w0 = *(const ulonglong2*)(wb + it * 2 * CPC);      // (j0,j1),(j2,j3)
            ulonglong2 w1 = *(const ulonglong2*)(wb + it * 2 * CPC + 4);  // (j4,j5),(j6,j7)
            u64 h0 = dup2(hv.x), h1 = dup2(hv.y), h2 = dup2(hv.z), h3 = dup2(hv.w);
            ffma2(acc[0][0], h0, w0.x); ffma2(acc[0][1], h0, w0.y);
            ffma2(acc[0][2], h0, w1.x); ffma2(acc[0][3], h0, w1.y);
            ffma2(acc[1][0], h1, w0.x); ffma2(acc[1][1], h1, w0.y);
            ffma2(acc[1][2], h1, w1.x); ffma2(acc[1][3], h1, w1.y);
            ffma2(acc[2][0], h2, w0.x); ffma2(acc[2][1], h2, w0.y);
            ffma2(acc[2][2], h2, w1.x); ffma2(acc[2][3], h2, w1.y);
            ffma2(acc[3][0], h3, w0.x); ffma2(acc[3][1], h3, w0.y);
            ffma2(acc[3][2], h3, w1.x); ffma2(acc[3][3], h3, w1.y);
        }

        // Stash partials: red[slot][b*9 + j]
        #pragma unroll
        for (int bi = 0; bi < 4; bi++) {
            float f[8];
            unpack2(acc[bi][0], f[0], f[1]);
            unpack2(acc[bi][1], f[2], f[3]);
            unpack2(acc[bi][2], f[4], f[5]);
            unpack2(acc[bi][3], f[6], f[7]);
            #pragma unroll
            for (int j = 0; j < 8; j++) rstore[bi * 9 + j] = f[j];
        }
        __syncthreads();

        // Final reduce (16 slots) + input proj + bias + tanh; write h_t [h][b].
        {
            float s0 = 0.f, s1 = 0.f;
            #pragma unroll
            for (int sl = 0; sl < NSLOT; sl++) {
                const float* rb = red + sl * SLOTSTRIDE + br * 9;
                s0 += rb[jr0];
                s1 += rb[jr0 + 4];
            }
            int tk = tok[br];
            const float* wx = W_xh + (size_t)tk * H + c0;
            float x0 = s0 + wx[jr0]     + bh0;
            float x1 = s1 + wx[jr0 + 4] + bh1;
            float* ho = g_hs + (size_t)t * H * B;
            ho[(size_t)(c0 + jr0)     * B + br] = tanh_safe(x0);
            ho[(size_t)(c0 + jr0 + 4) * B + br] = tanh_safe(x1);
        }

        grid_sync();
    }
}

// ---------------------------------------------------------------------------
// Output projection with FFMA2: out[b][t][o] = sum_h hs[t][h][b]*W_hy[h][o] + b_y[o]
// ---------------------------------------------------------------------------
__global__ void __launch_bounds__(256)
rnn_output_kernel(const float* __restrict__ W_hy,
                  const float* __restrict__ b_y,
                  float* __restrict__ out) {
    __shared__ float hc[64 * 64];    // [k][b]  16 KB
    __shared__ float Wc[64 * OUTD];  // [k][o]  32 KB

    const int t   = blockIdx.x;
    const int tid = threadIdx.x;
    const int b0  = (tid & 15) * 4;
    const int o0  = (tid >> 4) * 8;

    u64 acc[4][4];
    #pragma unroll
    for (int bi = 0; bi < 4; bi++)
        #pragma unroll
        for (int op = 0; op < 4; op++) acc[bi][op] = 0ull;

    const float* hsrc = g_hs + (size_t)t * H * B;

    for (int k0 = 0; k0 < H; k0 += 64) {
        const float4* hsv = (const float4*)(hsrc + (size_t)k0 * B);
        float4* hcv = (float4*)hc;
        #pragma unroll
        for (int i = 0; i < 4; i++) hcv[tid + i * 256] = hsv[tid + i * 256];

        const float4* wsv = (const float4*)(W_hy + (size_t)k0 * OUTD);
        float4* wcv = (float4*)Wc;
        #pragma unroll
        for (int i = 0; i < 8; i++) wcv[tid + i * 256] = wsv[tid + i * 256];

        __syncthreads();

        #pragma unroll 4
        for (int k = 0; k < 64; k++) {
            float4 hv = *(const float4*)(hc + k * 64 + b0);
            ulonglong2 wq0 = *(const ulonglong2*)(Wc + k * OUTD + o0);
            ulonglong2 wq1 = *(const ulonglong2*)(Wc + k * OUTD + o0 + 4);
            u64 h0 = dup2(hv.x), h1 = dup2(hv.y), h2 = dup2(hv.z), h3 = dup2(hv.w);
            ffma2(acc[0][0], h0, wq0.x); ffma2(acc[0][1], h0, wq0.y);
            ffma2(acc[0][2], h0, wq1.x); ffma2(acc[0][3], h0, wq1.y);
            ffma2(acc[1][0], h1, wq0.x); ffma2(acc[1][1], h1, wq0.y);
            ffma2(acc[1][2], h1, wq1.x); ffma2(acc[1][3], h1, wq1.y);
            ffma2(acc[2][0], h2, wq0.x); ffma2(acc[2][1], h2, wq0.y);
            ffma2(acc[2][2], h2, wq1.x); ffma2(acc[2][3], h2, wq1.y);
            ffma2(acc[3][0], h3, wq0.x); ffma2(acc[3][1], h3, wq0.y);
            ffma2(acc[3][2], h3, wq1.x); ffma2(acc[3][3], h3, wq1.y);
        }
        __syncthreads();
    }

    float byv[8];
    #pragma unroll
    for (int oi = 0; oi < 8; oi++) byv[oi] = b_y[o0 + oi];

    #pragma unroll
    for (int bi = 0; bi < 4; bi++) {
        float f[8];
        unpack2(acc[bi][0], f[0], f[1]);
        unpack2(acc[bi][1], f[2], f[3]);
        unpack2(acc[bi][2], f[4], f[5]);
        unpack2(acc[bi][3], f[6], f[7]);
        float* dst = out + ((size_t)(b0 + bi) * SEQ + t) * OUTD + o0;
        float4 v0, v1;
        v0.x = f[0] + byv[0]; v0.y = f[1] + byv[1];
        v0.z = f[2] + byv[2]; v0.w = f[3] + byv[3];
        v1.x = f[4] + byv[4]; v1.y = f[5] + byv[5];
        v1.z = f[6] + byv[6]; v1.w = f[7] + byv[7];
        *(float4*)(dst)     = v0;
        *(float4*)(dst + 4) = v1;
    }
}

// ---------------------------------------------------------------------------
// Launch. Inputs: X[i32 64x512], W_hh[f32 1024x1024], W_xh[f32 128x1024],
// W_hy[f32 1024x128], b_h[1024], b_y[128]. Output: f32 [64][512][128].
// ---------------------------------------------------------------------------
extern "C" void kernel_launch(void* const* d_in, const int* in_sizes, int n_in,
                              void* d_out, int out_size) {
    const int*   X    = (const int*)  d_in[0];
    const float* W_hh = (const float*)d_in[1];
    const float* W_xh = (const float*)d_in[2];
    const float* W_hy = (const float*)d_in[3];
    const float* b_h  = (const float*)d_in[4];
    const float* b_y  = (const float*)d_in[5];
    float* out = (float*)d_out;

    const int smem_rnn = (H * CPC + NSLOT * SLOTSTRIDE) * (int)sizeof(float)
                       + B * (int)sizeof(int);
    cudaFuncSetAttribute(rnn_recurrence_kernel,
                         cudaFuncAttributeMaxDynamicSharedMemorySize, smem_rnn);

    rnn_recurrence_kernel<<<G, NT, smem_rnn>>>(X, W_hh, W_xh, b_h);
    rnn_output_kernel<<<SEQ, 256>>>(W_hy, b_y, out);
}